// round 1
// baseline (speedup 1.0000x reference)
#include <cuda_runtime.h>
#include <cstdint>

#define N_NODES 50000
#define NREL    16
#define NBAS    16
#define DEMB    256
#define DHID    128
#define NEDGE   300000
#define NQUERY  100000
#define CAT     2176   // (1+NREL)*DHID

// ---------------- scratch (static __device__ globals; no allocation) ----------------
__device__ float g_Wcat[DEMB * CAT];                 // 2.2 MB (reused both layers)
__device__ float g_Z[(size_t)N_NODES * CAT];         // 435 MB transformed features
__device__ float g_acc[N_NODES * DHID];              // 25.6 MB accumulator
__device__ float g_x1[N_NODES * DHID];
__device__ float g_x2[N_NODES * DHID];
__device__ float g_HP[N_NODES * DHID];
__device__ float g_TP[N_NODES * DHID];
__device__ float g_rp[NREL * DHID];

// ---------------- W concat: [selfw | W_r = sum_b coeff[r,b]*bases[b]] ----------------
__global__ void build_wcat(const float* __restrict__ bases,
                           const float* __restrict__ coeff,
                           const float* __restrict__ selfw,
                           float* __restrict__ W, int din) {
    int idx = blockIdx.x * blockDim.x + threadIdx.x;
    if (idx >= din * CAT) return;
    int i = idx / CAT;
    int c = idx - i * CAT;
    int blk = c >> 7;           // 0 = self, 1..16 = relations
    int j = c & 127;
    float v;
    if (blk == 0) {
        v = selfw[i * DHID + j];
    } else {
        int r = blk - 1;
        v = 0.f;
        #pragma unroll
        for (int b = 0; b < NBAS; ++b)
            v += coeff[r * NBAS + b] * bases[((size_t)b * din + i) * DHID + j];
    }
    W[idx] = v;
}

// ---------------- generic fp32 SGEMM: C[M,N] = A[M,K] @ B[K,N] ----------------
// 128x128 block tile, BK=16, 8x8 per-thread microtile, 256 threads.
// Requires: K % 16 == 0, N % 128 == 0, lda/ldb/ldc % 4 == 0. M guarded.
__global__ __launch_bounds__(256) void sgemm(
    int M, int Ncols, int K,
    const float* __restrict__ A, int lda,
    const float* __restrict__ B, int ldb,
    float* __restrict__ C, int ldc)
{
    __shared__ float As[16][132];
    __shared__ float Bs[16][132];

    const int tid = threadIdx.x;
    const int tx = tid & 15;          // col group
    const int ty = tid >> 4;          // row group
    const int mBase = blockIdx.y * 128;
    const int nBase = blockIdx.x * 128;

    float acc[8][8];
    #pragma unroll
    for (int i = 0; i < 8; ++i)
        #pragma unroll
        for (int j = 0; j < 8; ++j) acc[i][j] = 0.f;

    for (int k0 = 0; k0 < K; k0 += 16) {
        // load A tile (128 rows x 16 k), transposed into As[k][row]
        #pragma unroll
        for (int it = 0; it < 2; ++it) {
            int idx = tid + it * 256;          // 0..511
            int arow = idx >> 2;               // 0..127
            int ak4 = (idx & 3) * 4;           // 0,4,8,12
            float4 v = make_float4(0.f, 0.f, 0.f, 0.f);
            int gr = mBase + arow;
            if (gr < M)
                v = *(const float4*)(A + (size_t)gr * lda + k0 + ak4);
            As[ak4 + 0][arow] = v.x;
            As[ak4 + 1][arow] = v.y;
            As[ak4 + 2][arow] = v.z;
            As[ak4 + 3][arow] = v.w;
        }
        // load B tile (16 k x 128 cols)
        #pragma unroll
        for (int it = 0; it < 2; ++it) {
            int idx = tid + it * 256;
            int brow = idx >> 5;               // 0..15
            int bc4 = (idx & 31) * 4;          // 0..124
            float4 v = *(const float4*)(B + (size_t)(k0 + brow) * ldb + nBase + bc4);
            *(float4*)&Bs[brow][bc4] = v;
        }
        __syncthreads();

        #pragma unroll
        for (int k = 0; k < 16; ++k) {
            float a[8], b[8];
            *(float4*)&a[0] = *(float4*)&As[k][ty * 8];
            *(float4*)&a[4] = *(float4*)&As[k][ty * 8 + 4];
            *(float4*)&b[0] = *(float4*)&Bs[k][tx * 8];
            *(float4*)&b[4] = *(float4*)&Bs[k][tx * 8 + 4];
            #pragma unroll
            for (int i = 0; i < 8; ++i)
                #pragma unroll
                for (int j = 0; j < 8; ++j)
                    acc[i][j] = fmaf(a[i], b[j], acc[i][j]);
        }
        __syncthreads();
    }

    #pragma unroll
    for (int i = 0; i < 8; ++i) {
        int gr = mBase + ty * 8 + i;
        if (gr < M) {
            float4 v0 = make_float4(acc[i][0], acc[i][1], acc[i][2], acc[i][3]);
            float4 v1 = make_float4(acc[i][4], acc[i][5], acc[i][6], acc[i][7]);
            float* cp = C + (size_t)gr * ldc + nBase + tx * 8;
            *(float4*)cp = v0;
            *(float4*)(cp + 4) = v1;
        }
    }
}

// ---------------- init accumulator from self-loop block of Z ----------------
__global__ void init_self(const float* __restrict__ Z, float* __restrict__ acc) {
    int idx = blockIdx.x * blockDim.x + threadIdx.x;
    if (idx >= N_NODES * DHID) return;
    int n = idx >> 7;
    int j = idx & 127;
    acc[idx] = Z[(size_t)n * CAT + j];
}

// ---------------- edge scatter: acc[row] += Z[col, block(etype)] ----------------
__global__ void edge_scatter(const int* __restrict__ erow,
                             const int* __restrict__ ecol,
                             const int* __restrict__ etype,
                             const float* __restrict__ Z,
                             float* __restrict__ acc) {
    int e = blockIdx.x * 8 + (threadIdx.x >> 5);
    if (e >= NEDGE) return;
    int lane = threadIdx.x & 31;
    int r = erow[e], c = ecol[e], t = etype[e];
    float4 v = ((const float4*)(Z + (size_t)c * CAT + (size_t)(1 + t) * DHID))[lane];
    float* dst = acc + (size_t)r * DHID + lane * 4;
    atomicAdd(dst + 0, v.x);
    atomicAdd(dst + 1, v.y);
    atomicAdd(dst + 2, v.z);
    atomicAdd(dst + 3, v.w);
}

// ---------------- relu + layernorm (one warp per node) ----------------
__global__ void relu_ln(const float* __restrict__ acc,
                        const float* __restrict__ gamma,
                        const float* __restrict__ beta,
                        float* __restrict__ out) {
    int n = blockIdx.x * 8 + (threadIdx.x >> 5);
    if (n >= N_NODES) return;
    int lane = threadIdx.x & 31;
    float4 v = ((const float4*)(acc + (size_t)n * DHID))[lane];
    v.x = fmaxf(v.x, 0.f); v.y = fmaxf(v.y, 0.f);
    v.z = fmaxf(v.z, 0.f); v.w = fmaxf(v.w, 0.f);
    float s = v.x + v.y + v.z + v.w;
    #pragma unroll
    for (int o = 16; o; o >>= 1) s += __shfl_xor_sync(0xFFFFFFFFu, s, o);
    float mu = s * (1.f / DHID);
    float dx = v.x - mu, dy = v.y - mu, dz = v.z - mu, dw = v.w - mu;
    float ss = dx * dx + dy * dy + dz * dz + dw * dw;
    #pragma unroll
    for (int o = 16; o; o >>= 1) ss += __shfl_xor_sync(0xFFFFFFFFu, ss, o);
    float inv = rsqrtf(ss * (1.f / DHID) + 1e-5f);
    float4 g = ((const float4*)gamma)[lane];
    float4 b = ((const float4*)beta)[lane];
    float4 o4;
    o4.x = dx * inv * g.x + b.x;
    o4.y = dy * inv * g.y + b.y;
    o4.z = dz * inv * g.z + b.z;
    o4.w = dw * inv * g.w + b.w;
    ((float4*)(out + (size_t)n * DHID))[lane] = o4;
}

// ---------------- relproj[r] = relation_emb[r] @ w1[128:384,:] + b1 ----------------
__global__ void relproj_k(const float* __restrict__ relemb,
                          const float* __restrict__ w1,
                          const float* __restrict__ b1,
                          float* __restrict__ rp) {
    int idx = blockIdx.x * blockDim.x + threadIdx.x;
    if (idx >= NREL * DHID) return;
    int r = idx >> 7;
    int j = idx & 127;
    float s = b1[j];
    for (int i = 0; i < DEMB; ++i)
        s = fmaf(relemb[r * DEMB + i], w1[(DHID + i) * DHID + j], s);
    rp[idx] = s;
}

// ---------------- score: out[q] = relu(HP[h]+TP[t]+rp[r]) . w2 + b2 ----------------
__global__ void score_k(const int* __restrict__ head,
                        const int* __restrict__ rel,
                        const int* __restrict__ tail,
                        const float* __restrict__ HP,
                        const float* __restrict__ TP,
                        const float* __restrict__ rp,
                        const float* __restrict__ w2,
                        const float* __restrict__ b2,
                        float* __restrict__ out) {
    int q = blockIdx.x * 8 + (threadIdx.x >> 5);
    if (q >= NQUERY) return;
    int lane = threadIdx.x & 31;
    int h = head[q], r = rel[q], t = tail[q];
    float4 a = ((const float4*)(HP + (size_t)h * DHID))[lane];
    float4 bb = ((const float4*)(TP + (size_t)t * DHID))[lane];
    float4 c = ((const float4*)(rp + (size_t)r * DHID))[lane];
    float4 w = ((const float4*)w2)[lane];
    float s = fmaxf(a.x + bb.x + c.x, 0.f) * w.x
            + fmaxf(a.y + bb.y + c.y, 0.f) * w.y
            + fmaxf(a.z + bb.z + c.z, 0.f) * w.z
            + fmaxf(a.w + bb.w + c.w, 0.f) * w.w;
    #pragma unroll
    for (int o = 16; o; o >>= 1) s += __shfl_xor_sync(0xFFFFFFFFu, s, o);
    if (lane == 0) out[q] = s + b2[0];
}

// ---------------- launch ----------------
extern "C" void kernel_launch(void* const* d_in, const int* in_sizes, int n_in,
                              void* d_out, int out_size) {
    (void)in_sizes; (void)n_in; (void)out_size;
    const int*   edge_index   = (const int*)d_in[0];
    const int*   edge_type    = (const int*)d_in[1];
    const int*   head_ids     = (const int*)d_in[2];
    const int*   relation_ids = (const int*)d_in[3];
    const int*   tail_ids     = (const int*)d_in[4];
    const float* entity_emb   = (const float*)d_in[5];
    const float* relation_emb = (const float*)d_in[6];
    const float* bases0       = (const float*)d_in[7];
    const float* coeff0       = (const float*)d_in[8];
    const float* selfw0       = (const float*)d_in[9];
    const float* bases1       = (const float*)d_in[10];
    const float* coeff1       = (const float*)d_in[11];
    const float* selfw1       = (const float*)d_in[12];
    const float* ln0_g        = (const float*)d_in[13];
    const float* ln0_b        = (const float*)d_in[14];
    const float* ln1_g        = (const float*)d_in[15];
    const float* ln1_b        = (const float*)d_in[16];
    const float* w1           = (const float*)d_in[17];
    const float* b1           = (const float*)d_in[18];
    const float* w2           = (const float*)d_in[19];
    const float* b2           = (const float*)d_in[20];
    float* out = (float*)d_out;

    float *Wcat, *Z, *acc, *x1, *x2, *HP, *TP, *rp;
    cudaGetSymbolAddress((void**)&Wcat, g_Wcat);
    cudaGetSymbolAddress((void**)&Z,    g_Z);
    cudaGetSymbolAddress((void**)&acc,  g_acc);
    cudaGetSymbolAddress((void**)&x1,   g_x1);
    cudaGetSymbolAddress((void**)&x2,   g_x2);
    cudaGetSymbolAddress((void**)&HP,   g_HP);
    cudaGetSymbolAddress((void**)&TP,   g_TP);
    cudaGetSymbolAddress((void**)&rp,   g_rp);

    const int* erow = edge_index;
    const int* ecol = edge_index + NEDGE;

    dim3 gz(CAT / 128, (N_NODES + 127) / 128);   // 17 x 391
    dim3 gh(1, (N_NODES + 127) / 128);

    // ----- layer 0 -----
    build_wcat<<<(DEMB * CAT + 255) / 256, 256>>>(bases0, coeff0, selfw0, Wcat, DEMB);
    sgemm<<<gz, 256>>>(N_NODES, CAT, DEMB, entity_emb, DEMB, Wcat, CAT, Z, CAT);
    init_self<<<(N_NODES * DHID + 255) / 256, 256>>>(Z, acc);
    edge_scatter<<<(NEDGE + 7) / 8, 256>>>(erow, ecol, edge_type, Z, acc);
    relu_ln<<<(N_NODES + 7) / 8, 256>>>(acc, ln0_g, ln0_b, x1);

    // ----- layer 1 -----
    build_wcat<<<(DHID * CAT + 255) / 256, 256>>>(bases1, coeff1, selfw1, Wcat, DHID);
    sgemm<<<gz, 256>>>(N_NODES, CAT, DHID, x1, DHID, Wcat, CAT, Z, CAT);
    init_self<<<(N_NODES * DHID + 255) / 256, 256>>>(Z, acc);
    edge_scatter<<<(NEDGE + 7) / 8, 256>>>(erow, ecol, edge_type, Z, acc);
    relu_ln<<<(N_NODES + 7) / 8, 256>>>(acc, ln1_g, ln1_b, x2);

    // ----- scoring -----
    relproj_k<<<(NREL * DHID + 255) / 256, 256>>>(relation_emb, w1, b1, rp);
    sgemm<<<gh, 256>>>(N_NODES, DHID, DHID, x2, DHID, w1, DHID, HP, DHID);               // head block
    sgemm<<<gh, 256>>>(N_NODES, DHID, DHID, x2, DHID, w1 + 384 * DHID, DHID, TP, DHID);  // tail block
    score_k<<<(NQUERY + 7) / 8, 256>>>(head_ids, relation_ids, tail_ids, HP, TP, rp, w2, b2, out);
}

// round 3
// speedup vs baseline: 1.7404x; 1.7404x over previous
#include <cuda_runtime.h>
#include <cuda_bf16.h>
#include <cstdint>

#define N_NODES 50000
#define NREL    16
#define NBAS    16
#define DEMB    256
#define DHID    128
#define NEDGE   300000
#define NQUERY  100000
#define CAT     2176   // (1+NREL)*DHID

// ---------------- scratch (static __device__ globals; no allocation) ----------------
__device__ float g_WcatT[(size_t)CAT * DEMB];        // transposed weights [CAT][din]
__device__ float g_Z[(size_t)N_NODES * CAT];         // transformed features
__device__ float g_acc[N_NODES * DHID];
__device__ float g_x1[N_NODES * DHID];
__device__ float g_x2[N_NODES * DHID];
__device__ float g_HP[N_NODES * DHID];
__device__ float g_TP[N_NODES * DHID];
__device__ float g_rp[NREL * DHID];
__device__ float g_w1hT[DHID * DHID];
__device__ float g_w1tT[DHID * DHID];

__device__ __forceinline__ uint32_t smem_u32(const void* p) {
    uint32_t a;
    asm("{ .reg .u64 t; cvta.to.shared.u64 t, %1; cvt.u32.u64 %0, t; }" : "=r"(a) : "l"(p));
    return a;
}
__device__ __forceinline__ uint32_t pack_bf2(__nv_bfloat16 a, __nv_bfloat16 b) {
    return ((uint32_t)__bfloat16_as_ushort(b) << 16) | __bfloat16_as_ushort(a);
}
__device__ __forceinline__ void ldsm4(uint32_t* r, uint32_t addr) {
    asm volatile("ldmatrix.sync.aligned.m8n8.x4.shared.b16 {%0,%1,%2,%3}, [%4];"
                 : "=r"(r[0]), "=r"(r[1]), "=r"(r[2]), "=r"(r[3]) : "r"(addr));
}
__device__ __forceinline__ void mma_bf16(float* d, const uint32_t* a, uint32_t b0, uint32_t b1) {
    asm volatile(
        "mma.sync.aligned.m16n8k16.row.col.f32.bf16.bf16.f32 "
        "{%0,%1,%2,%3}, {%4,%5,%6,%7}, {%8,%9}, {%0,%1,%2,%3};"
        : "+f"(d[0]), "+f"(d[1]), "+f"(d[2]), "+f"(d[3])
        : "r"(a[0]), "r"(a[1]), "r"(a[2]), "r"(a[3]), "r"(b0), "r"(b1));
}

// ============================================================================
// 3xBF16 mma.sync GEMM: C[M,N] = A[M,K] @ Bt[N,K]^T
// grid (N/128, ceil(M/128)), 256 threads, BK=64
// smem tiles: [128 rows][64 bf16] = 128B/row, 16B-seg swizzle (seg ^= row&7)
// ============================================================================
#define TILE_B 16384                      // bytes per smem tile
#define GEMM_SMEM (4 * TILE_B)

__global__ __launch_bounds__(256, 2)
void gemm3x(int M, int K,
            const float* __restrict__ A, int lda,
            const float* __restrict__ Bt, int ldb,
            float* __restrict__ C, int ldc)
{
    extern __shared__ char sm[];
    char* sAhi = sm;
    char* sAlo = sm + TILE_B;
    char* sBhi = sm + 2 * TILE_B;
    char* sBlo = sm + 3 * TILE_B;
    const uint32_t bAhi = smem_u32(sAhi);
    const uint32_t bAlo = bAhi + TILE_B;
    const uint32_t bBhi = bAhi + 2 * TILE_B;
    const uint32_t bBlo = bAhi + 3 * TILE_B;

    const int tid  = threadIdx.x;
    const int wid  = tid >> 5;
    const int lane = tid & 31;
    const int wm   = wid & 3;            // m warp: 0..3 (32 rows each)
    const int wn   = wid >> 2;           // n warp: 0..1 (64 cols each)
    const int mBase = blockIdx.y * 128;
    const int nBase = blockIdx.x * 128;

    float d[2][8][4];
    #pragma unroll
    for (int i = 0; i < 2; ++i)
        #pragma unroll
        for (int j = 0; j < 8; ++j)
            #pragma unroll
            for (int t = 0; t < 4; ++t) d[i][j][t] = 0.f;

    // staging index: each thread writes 4 floats->4 bf16 (8B) per iter
    const int srow = tid >> 4;           // 0..15 (+16*it)
    const int sc4  = (tid & 15) * 4;     // float col 0..60
    const int kbyte = sc4 * 2;           // 0..120
    const uint32_t soff_base = (uint32_t)(((kbyte >> 4)) << 4) + (kbyte & 15);

    // ldmatrix addresses (constant per thread, per tile-base)
    const int lrow = lane & 15;
    const int lkh  = lane >> 4;          // 0/1 -> k half (16B seg step)

    for (int k0 = 0; k0 < K; k0 += 64) {
        __syncthreads();
        // ---- stage A (128 x 64) hi/lo ----
        #pragma unroll
        for (int it = 0; it < 8; ++it) {
            int row = srow + it * 16;
            float4 v = make_float4(0.f, 0.f, 0.f, 0.f);
            int gr = mBase + row;
            if (gr < M) v = *(const float4*)(A + (size_t)gr * lda + k0 + sc4);
            __nv_bfloat16 h0 = __float2bfloat16(v.x), h1 = __float2bfloat16(v.y);
            __nv_bfloat16 h2 = __float2bfloat16(v.z), h3 = __float2bfloat16(v.w);
            __nv_bfloat16 l0 = __float2bfloat16(v.x - __bfloat162float(h0));
            __nv_bfloat16 l1 = __float2bfloat16(v.y - __bfloat162float(h1));
            __nv_bfloat16 l2 = __float2bfloat16(v.z - __bfloat162float(h2));
            __nv_bfloat16 l3 = __float2bfloat16(v.w - __bfloat162float(h3));
            uint32_t seg = (uint32_t)(kbyte >> 4) ^ (uint32_t)(row & 7);
            uint32_t off = (uint32_t)(row * 128) + (seg << 4) + (uint32_t)(kbyte & 15);
            *(uint2*)(sAhi + off) = make_uint2(pack_bf2(h0, h1), pack_bf2(h2, h3));
            *(uint2*)(sAlo + off) = make_uint2(pack_bf2(l0, l1), pack_bf2(l2, l3));
        }
        // ---- stage B (128 x 64) hi/lo ----
        #pragma unroll
        for (int it = 0; it < 8; ++it) {
            int row = srow + it * 16;
            float4 v = *(const float4*)(Bt + (size_t)(nBase + row) * ldb + k0 + sc4);
            __nv_bfloat16 h0 = __float2bfloat16(v.x), h1 = __float2bfloat16(v.y);
            __nv_bfloat16 h2 = __float2bfloat16(v.z), h3 = __float2bfloat16(v.w);
            __nv_bfloat16 l0 = __float2bfloat16(v.x - __bfloat162float(h0));
            __nv_bfloat16 l1 = __float2bfloat16(v.y - __bfloat162float(h1));
            __nv_bfloat16 l2 = __float2bfloat16(v.z - __bfloat162float(h2));
            __nv_bfloat16 l3 = __float2bfloat16(v.w - __bfloat162float(h3));
            uint32_t seg = (uint32_t)(kbyte >> 4) ^ (uint32_t)(row & 7);
            uint32_t off = (uint32_t)(row * 128) + (seg << 4) + (uint32_t)(kbyte & 15);
            *(uint2*)(sBhi + off) = make_uint2(pack_bf2(h0, h1), pack_bf2(h2, h3));
            *(uint2*)(sBlo + off) = make_uint2(pack_bf2(l0, l1), pack_bf2(l2, l3));
        }
        __syncthreads();

        // ---- compute: 4 k16 steps ----
        #pragma unroll
        for (int ks = 0; ks < 4; ++ks) {
            uint32_t ah[2][4], al[2][4];
            #pragma unroll
            for (int i = 0; i < 2; ++i) {
                int row = wm * 32 + i * 16 + lrow;
                uint32_t seg = (uint32_t)(ks * 2 + lkh) ^ (uint32_t)(row & 7);
                uint32_t off = (uint32_t)(row * 128) + (seg << 4);
                ldsm4(ah[i], bAhi + off);
                ldsm4(al[i], bAlo + off);
            }
            #pragma unroll
            for (int j2 = 0; j2 < 4; ++j2) {
                uint32_t bh[4], bl[4];
                int row = wn * 64 + j2 * 16 + lrow;
                uint32_t seg = (uint32_t)(ks * 2 + lkh) ^ (uint32_t)(row & 7);
                uint32_t off = (uint32_t)(row * 128) + (seg << 4);
                ldsm4(bh, bBhi + off);
                ldsm4(bl, bBlo + off);
                #pragma unroll
                for (int i = 0; i < 2; ++i) {
                    mma_bf16(d[i][j2 * 2],     ah[i], bh[0], bh[2]);
                    mma_bf16(d[i][j2 * 2],     ah[i], bl[0], bl[2]);
                    mma_bf16(d[i][j2 * 2],     al[i], bh[0], bh[2]);
                    mma_bf16(d[i][j2 * 2 + 1], ah[i], bh[1], bh[3]);
                    mma_bf16(d[i][j2 * 2 + 1], ah[i], bl[1], bl[3]);
                    mma_bf16(d[i][j2 * 2 + 1], al[i], bh[1], bh[3]);
                }
            }
        }
    }

    // ---- epilogue: write C ----
    const int q = lane >> 2;             // row-in-8
    const int cpair = (lane & 3) * 2;
    #pragma unroll
    for (int i = 0; i < 2; ++i) {
        int gr0 = mBase + wm * 32 + i * 16 + q;
        #pragma unroll
        for (int j = 0; j < 8; ++j) {
            int gc = nBase + wn * 64 + j * 8 + cpair;
            if (gr0 < M)
                *(float2*)(C + (size_t)gr0 * ldc + gc) = make_float2(d[i][j][0], d[i][j][1]);
            if (gr0 + 8 < M)
                *(float2*)(C + (size_t)(gr0 + 8) * ldc + gc) = make_float2(d[i][j][2], d[i][j][3]);
        }
    }
}

// ---------------- WcatT: [CAT rows][din cols]; row n = col n of [selfw | W_r] ----------------
__global__ void build_wcatT(const float* __restrict__ bases,
                            const float* __restrict__ coeff,
                            const float* __restrict__ selfw,
                            float* __restrict__ WT, int din) {
    int idx = blockIdx.x * blockDim.x + threadIdx.x;
    if (idx >= CAT * din) return;
    int n = idx / din;
    int k = idx - n * din;
    int blk = n >> 7;
    int j = n & 127;
    float v;
    if (blk == 0) {
        v = selfw[k * DHID + j];
    } else {
        int r = blk - 1;
        v = 0.f;
        #pragma unroll
        for (int b = 0; b < NBAS; ++b)
            v += coeff[r * NBAS + b] * bases[((size_t)b * din + k) * DHID + j];
    }
    WT[idx] = v;
}

// ---------------- transpose head/tail blocks of w1 into [N=128][K=128] ----------------
__global__ void transpose_w1(const float* __restrict__ w1,
                             float* __restrict__ hT, float* __restrict__ tT) {
    int idx = blockIdx.x * blockDim.x + threadIdx.x;
    if (idx >= DHID * DHID) return;
    int n = idx >> 7;
    int k = idx & 127;
    hT[n * DHID + k] = w1[(size_t)k * DHID + n];
    tT[n * DHID + k] = w1[(size_t)(384 + k) * DHID + n];
}

// ---------------- init accumulator from self-loop block of Z ----------------
__global__ void init_self(const float* __restrict__ Z, float* __restrict__ acc) {
    int idx = blockIdx.x * blockDim.x + threadIdx.x;
    if (idx >= N_NODES * DHID) return;
    int n = idx >> 7;
    int j = idx & 127;
    acc[idx] = Z[(size_t)n * CAT + j];
}

// ---------------- edge scatter: acc[row] += Z[col, block(etype)] ----------------
__global__ void edge_scatter(const int* __restrict__ erow,
                             const int* __restrict__ ecol,
                             const int* __restrict__ etype,
                             const float* __restrict__ Z,
                             float* __restrict__ acc) {
    int e = blockIdx.x * 8 + (threadIdx.x >> 5);
    if (e >= NEDGE) return;
    int lane = threadIdx.x & 31;
    int r = erow[e], c = ecol[e], t = etype[e];
    float4 v = ((const float4*)(Z + (size_t)c * CAT + (size_t)(1 + t) * DHID))[lane];
    float* dst = acc + (size_t)r * DHID + lane * 4;
    atomicAdd(dst + 0, v.x);
    atomicAdd(dst + 1, v.y);
    atomicAdd(dst + 2, v.z);
    atomicAdd(dst + 3, v.w);
}

// ---------------- relu + layernorm (one warp per node) ----------------
__global__ void relu_ln(const float* __restrict__ acc,
                        const float* __restrict__ gamma,
                        const float* __restrict__ beta,
                        float* __restrict__ out) {
    int n = blockIdx.x * 8 + (threadIdx.x >> 5);
    if (n >= N_NODES) return;
    int lane = threadIdx.x & 31;
    float4 v = ((const float4*)(acc + (size_t)n * DHID))[lane];
    v.x = fmaxf(v.x, 0.f); v.y = fmaxf(v.y, 0.f);
    v.z = fmaxf(v.z, 0.f); v.w = fmaxf(v.w, 0.f);
    float s = v.x + v.y + v.z + v.w;
    #pragma unroll
    for (int o = 16; o; o >>= 1) s += __shfl_xor_sync(0xFFFFFFFFu, s, o);
    float mu = s * (1.f / DHID);
    float dx = v.x - mu, dy = v.y - mu, dz = v.z - mu, dw = v.w - mu;
    float ss = dx * dx + dy * dy + dz * dz + dw * dw;
    #pragma unroll
    for (int o = 16; o; o >>= 1) ss += __shfl_xor_sync(0xFFFFFFFFu, ss, o);
    float inv = rsqrtf(ss * (1.f / DHID) + 1e-5f);
    float4 g = ((const float4*)gamma)[lane];
    float4 b = ((const float4*)beta)[lane];
    float4 o4;
    o4.x = dx * inv * g.x + b.x;
    o4.y = dy * inv * g.y + b.y;
    o4.z = dz * inv * g.z + b.z;
    o4.w = dw * inv * g.w + b.w;
    ((float4*)(out + (size_t)n * DHID))[lane] = o4;
}

// ---------------- relproj[r] = relation_emb[r] @ w1[128:384,:] + b1 ----------------
__global__ void relproj_k(const float* __restrict__ relemb,
                          const float* __restrict__ w1,
                          const float* __restrict__ b1,
                          float* __restrict__ rp) {
    int idx = blockIdx.x * blockDim.x + threadIdx.x;
    if (idx >= NREL * DHID) return;
    int r = idx >> 7;
    int j = idx & 127;
    float s = b1[j];
    for (int i = 0; i < DEMB; ++i)
        s = fmaf(relemb[r * DEMB + i], w1[(DHID + i) * DHID + j], s);
    rp[idx] = s;
}

// ---------------- score ----------------
__global__ void score_k(const int* __restrict__ head,
                        const int* __restrict__ rel,
                        const int* __restrict__ tail,
                        const float* __restrict__ HP,
                        const float* __restrict__ TP,
                        const float* __restrict__ rp,
                        const float* __restrict__ w2,
                        const float* __restrict__ b2,
                        float* __restrict__ out) {
    int q = blockIdx.x * 8 + (threadIdx.x >> 5);
    if (q >= NQUERY) return;
    int lane = threadIdx.x & 31;
    int h = head[q], r = rel[q], t = tail[q];
    float4 a = ((const float4*)(HP + (size_t)h * DHID))[lane];
    float4 bb = ((const float4*)(TP + (size_t)t * DHID))[lane];
    float4 c = ((const float4*)(rp + (size_t)r * DHID))[lane];
    float4 w = ((const float4*)w2)[lane];
    float s = fmaxf(a.x + bb.x + c.x, 0.f) * w.x
            + fmaxf(a.y + bb.y + c.y, 0.f) * w.y
            + fmaxf(a.z + bb.z + c.z, 0.f) * w.z
            + fmaxf(a.w + bb.w + c.w, 0.f) * w.w;
    #pragma unroll
    for (int o = 16; o; o >>= 1) s += __shfl_xor_sync(0xFFFFFFFFu, s, o);
    if (lane == 0) out[q] = s + b2[0];
}

// ---------------- launch ----------------
extern "C" void kernel_launch(void* const* d_in, const int* in_sizes, int n_in,
                              void* d_out, int out_size) {
    (void)in_sizes; (void)n_in; (void)out_size;
    const int*   edge_index   = (const int*)d_in[0];
    const int*   edge_type    = (const int*)d_in[1];
    const int*   head_ids     = (const int*)d_in[2];
    const int*   relation_ids = (const int*)d_in[3];
    const int*   tail_ids     = (const int*)d_in[4];
    const float* entity_emb   = (const float*)d_in[5];
    const float* relation_emb = (const float*)d_in[6];
    const float* bases0       = (const float*)d_in[7];
    const float* coeff0       = (const float*)d_in[8];
    const float* selfw0       = (const float*)d_in[9];
    const float* bases1       = (const float*)d_in[10];
    const float* coeff1       = (const float*)d_in[11];
    const float* selfw1       = (const float*)d_in[12];
    const float* ln0_g        = (const float*)d_in[13];
    const float* ln0_b        = (const float*)d_in[14];
    const float* ln1_g        = (const float*)d_in[15];
    const float* ln1_b        = (const float*)d_in[16];
    const float* w1           = (const float*)d_in[17];
    const float* b1           = (const float*)d_in[18];
    const float* w2           = (const float*)d_in[19];
    const float* b2           = (const float*)d_in[20];
    float* out = (float*)d_out;

    float *WT, *Z, *acc, *x1, *x2, *HP, *TP, *rp, *w1hT, *w1tT;
    cudaGetSymbolAddress((void**)&WT,   g_WcatT);
    cudaGetSymbolAddress((void**)&Z,    g_Z);
    cudaGetSymbolAddress((void**)&acc,  g_acc);
    cudaGetSymbolAddress((void**)&x1,   g_x1);
    cudaGetSymbolAddress((void**)&x2,   g_x2);
    cudaGetSymbolAddress((void**)&HP,   g_HP);
    cudaGetSymbolAddress((void**)&TP,   g_TP);
    cudaGetSymbolAddress((void**)&rp,   g_rp);
    cudaGetSymbolAddress((void**)&w1hT, g_w1hT);
    cudaGetSymbolAddress((void**)&w1tT, g_w1tT);

    cudaFuncSetAttribute(gemm3x, cudaFuncAttributeMaxDynamicSharedMemorySize, GEMM_SMEM);

    const int* erow = edge_index;
    const int* ecol = edge_index + NEDGE;

    dim3 gz(CAT / 128, (N_NODES + 127) / 128);   // 17 x 391
    dim3 gh(1, (N_NODES + 127) / 128);

    // ----- layer 0 -----
    build_wcatT<<<(CAT * DEMB + 255) / 256, 256>>>(bases0, coeff0, selfw0, WT, DEMB);
    gemm3x<<<gz, 256, GEMM_SMEM>>>(N_NODES, DEMB, entity_emb, DEMB, WT, DEMB, Z, CAT);
    init_self<<<(N_NODES * DHID + 255) / 256, 256>>>(Z, acc);
    edge_scatter<<<(NEDGE + 7) / 8, 256>>>(erow, ecol, edge_type, Z, acc);
    relu_ln<<<(N_NODES + 7) / 8, 256>>>(acc, ln0_g, ln0_b, x1);

    // ----- layer 1 -----
    build_wcatT<<<(CAT * DHID + 255) / 256, 256>>>(bases1, coeff1, selfw1, WT, DHID);
    gemm3x<<<gz, 256, GEMM_SMEM>>>(N_NODES, DHID, x1, DHID, WT, DHID, Z, CAT);
    init_self<<<(N_NODES * DHID + 255) / 256, 256>>>(Z, acc);
    edge_scatter<<<(NEDGE + 7) / 8, 256>>>(erow, ecol, edge_type, Z, acc);
    relu_ln<<<(N_NODES + 7) / 8, 256>>>(acc, ln1_g, ln1_b, x2);

    // ----- scoring -----
    relproj_k<<<(NREL * DHID + 255) / 256, 256>>>(relation_emb, w1, b1, rp);
    transpose_w1<<<(DHID * DHID + 255) / 256, 256>>>(w1, w1hT, w1tT);
    gemm3x<<<gh, 256, GEMM_SMEM>>>(N_NODES, DHID, x2, DHID, w1hT, DHID, HP, DHID);
    gemm3x<<<gh, 256, GEMM_SMEM>>>(N_NODES, DHID, x2, DHID, w1tT, DHID, TP, DHID);
    score_k<<<(NQUERY + 7) / 8, 256>>>(head_ids, relation_ids, tail_ids, HP, TP, rp, w2, b2, out);
}

// round 4
// speedup vs baseline: 1.8311x; 1.0521x over previous
#include <cuda_runtime.h>
#include <cuda_bf16.h>
#include <cstdint>

#define N_NODES 50000
#define NREL    16
#define NBAS    16
#define DEMB    256
#define DHID    128
#define NEDGE   300000
#define NQUERY  100000
#define CAT     2176   // (1+NREL)*DHID

// ---------------- scratch (static __device__ globals; no allocation) ----------------
__device__ __nv_bfloat16 g_Ehi[(size_t)N_NODES * DEMB];
__device__ __nv_bfloat16 g_Elo[(size_t)N_NODES * DEMB];
__device__ __nv_bfloat16 g_Whi[(size_t)CAT * DEMB];
__device__ __nv_bfloat16 g_Wlo[(size_t)CAT * DEMB];
__device__ __nv_bfloat16 g_xhi[N_NODES * DHID];
__device__ __nv_bfloat16 g_xlo[N_NODES * DHID];
__device__ __nv_bfloat16 g_w1hTh[DHID * DHID];
__device__ __nv_bfloat16 g_w1hTl[DHID * DHID];
__device__ __nv_bfloat16 g_w1tTh[DHID * DHID];
__device__ __nv_bfloat16 g_w1tTl[DHID * DHID];
__device__ float g_Z[(size_t)N_NODES * CAT];
__device__ float g_acc[N_NODES * DHID];
__device__ float g_HP[N_NODES * DHID];
__device__ float g_TP[N_NODES * DHID];
__device__ float g_rp[NREL * DHID];

__device__ __forceinline__ uint32_t smem_u32(const void* p) {
    uint32_t a;
    asm("{ .reg .u64 t; cvta.to.shared.u64 t, %1; cvt.u32.u64 %0, t; }" : "=r"(a) : "l"(p));
    return a;
}
__device__ __forceinline__ uint32_t pack_bf2(__nv_bfloat16 a, __nv_bfloat16 b) {
    return ((uint32_t)__bfloat16_as_ushort(b) << 16) | __bfloat16_as_ushort(a);
}
__device__ __forceinline__ void ldsm4(uint32_t* r, uint32_t addr) {
    asm volatile("ldmatrix.sync.aligned.m8n8.x4.shared.b16 {%0,%1,%2,%3}, [%4];"
                 : "=r"(r[0]), "=r"(r[1]), "=r"(r[2]), "=r"(r[3]) : "r"(addr));
}
__device__ __forceinline__ void mma_bf16(float* d, const uint32_t* a, uint32_t b0, uint32_t b1) {
    asm volatile(
        "mma.sync.aligned.m16n8k16.row.col.f32.bf16.bf16.f32 "
        "{%0,%1,%2,%3}, {%4,%5,%6,%7}, {%8,%9}, {%0,%1,%2,%3};"
        : "+f"(d[0]), "+f"(d[1]), "+f"(d[2]), "+f"(d[3])
        : "r"(a[0]), "r"(a[1]), "r"(a[2]), "r"(a[3]), "r"(b0), "r"(b1));
}
__device__ __forceinline__ void cp16(uint32_t dst, const void* src, int srcBytes) {
    asm volatile("cp.async.cg.shared.global [%0], [%1], 16, %2;"
                 :: "r"(dst), "l"(src), "r"(srcBytes));
}
#define CP_COMMIT() asm volatile("cp.async.commit_group;" ::: "memory")
template<int Nw> __device__ __forceinline__ void cp_wait() {
    asm volatile("cp.async.wait_group %0;" :: "n"(Nw) : "memory");
}

// hi/lo split of one float
__device__ __forceinline__ void split1(float v, __nv_bfloat16& h, __nv_bfloat16& l) {
    h = __float2bfloat16(v);
    l = __float2bfloat16(v - __bfloat162float(h));
}

// ============================================================================
// 3xBF16 mma.sync GEMM, cp.async double-buffered.
// C[M,N] = A[M,K] @ Bt[N,K]^T ; A,B pre-split bf16 hi/lo, row-major stride K.
// grid (N/128, ceil(M/128)), 256 threads, BK=64.
// smem per stage: 4 tiles x [128 rows][64 bf16] (128B/row, 16B-seg swizzle).
// ============================================================================
#define TILE_B  16384
#define STAGE_B (4 * TILE_B)          // 64 KB
#define GEMM_SMEM (2 * STAGE_B)       // 128 KB

__global__ __launch_bounds__(256, 1)
void gemm3xb(int M, int K,
             const __nv_bfloat16* __restrict__ Ahi,
             const __nv_bfloat16* __restrict__ Alo,
             const __nv_bfloat16* __restrict__ Bhi,
             const __nv_bfloat16* __restrict__ Blo,
             float* __restrict__ C, int ldc)
{
    extern __shared__ char sm[];
    const uint32_t sbase = smem_u32(sm);

    const int tid  = threadIdx.x;
    const int wid  = tid >> 5;
    const int lane = tid & 31;
    const int wm   = wid & 3;
    const int wn   = wid >> 2;
    const int mBase = blockIdx.y * 128;
    const int nBase = blockIdx.x * 128;

    float d[2][8][4];
    #pragma unroll
    for (int i = 0; i < 2; ++i)
        #pragma unroll
        for (int j = 0; j < 8; ++j)
            #pragma unroll
            for (int t = 0; t < 4; ++t) d[i][j][t] = 0.f;

    const int nk = K >> 6;

    // staging: 1024 16B-chunks per tile, 4 per thread per tile
    // chunk g: row = g>>3, seg = g&7 ; smem seg' = seg ^ (row&7)
    auto issue = [&](int s, int k0) {
        const uint32_t sb = sbase + (uint32_t)s * STAGE_B;
        #pragma unroll
        for (int it = 0; it < 4; ++it) {
            int g = tid + it * 256;
            int row = g >> 3;
            int seg = g & 7;
            uint32_t soff = (uint32_t)(row * 128) + ((uint32_t)(seg ^ (row & 7)) << 4);
            int gr = mBase + row;
            int okA = (gr < M) ? 16 : 0;
            size_t aoff = (size_t)(okA ? gr : 0) * K + k0 + seg * 8;
            cp16(sb + soff,              Ahi + aoff, okA);
            cp16(sb + TILE_B + soff,     Alo + aoff, okA);
            size_t boff = (size_t)(nBase + row) * K + k0 + seg * 8;
            cp16(sb + 2 * TILE_B + soff, Bhi + boff, 16);
            cp16(sb + 3 * TILE_B + soff, Blo + boff, 16);
        }
    };

    const int lrow = lane & 15;
    const int lkh  = lane >> 4;

    issue(0, 0);
    CP_COMMIT();

    for (int c = 0; c < nk; ++c) {
        if (c + 1 < nk) {
            issue((c + 1) & 1, (c + 1) << 6);
            CP_COMMIT();
            cp_wait<1>();
        } else {
            cp_wait<0>();
        }
        __syncthreads();

        const uint32_t bAhi = sbase + (uint32_t)(c & 1) * STAGE_B;
        const uint32_t bAlo = bAhi + TILE_B;
        const uint32_t bBhi = bAhi + 2 * TILE_B;
        const uint32_t bBlo = bAhi + 3 * TILE_B;

        #pragma unroll
        for (int ks = 0; ks < 4; ++ks) {
            uint32_t ah[2][4], al[2][4];
            #pragma unroll
            for (int i = 0; i < 2; ++i) {
                int row = wm * 32 + i * 16 + lrow;
                uint32_t seg = (uint32_t)(ks * 2 + lkh) ^ (uint32_t)(row & 7);
                uint32_t off = (uint32_t)(row * 128) + (seg << 4);
                ldsm4(ah[i], bAhi + off);
                ldsm4(al[i], bAlo + off);
            }
            #pragma unroll
            for (int j2 = 0; j2 < 4; ++j2) {
                uint32_t bh[4], bl[4];
                int row = wn * 64 + j2 * 16 + lrow;
                uint32_t seg = (uint32_t)(ks * 2 + lkh) ^ (uint32_t)(row & 7);
                uint32_t off = (uint32_t)(row * 128) + (seg << 4);
                ldsm4(bh, bBhi + off);
                ldsm4(bl, bBlo + off);
                #pragma unroll
                for (int i = 0; i < 2; ++i) {
                    mma_bf16(d[i][j2 * 2],     ah[i], bh[0], bh[2]);
                    mma_bf16(d[i][j2 * 2],     ah[i], bl[0], bl[2]);
                    mma_bf16(d[i][j2 * 2],     al[i], bh[0], bh[2]);
                    mma_bf16(d[i][j2 * 2 + 1], ah[i], bh[1], bh[3]);
                    mma_bf16(d[i][j2 * 2 + 1], ah[i], bl[1], bl[3]);
                    mma_bf16(d[i][j2 * 2 + 1], al[i], bh[1], bh[3]);
                }
            }
        }
        __syncthreads();
    }

    // ---- epilogue ----
    const int q = lane >> 2;
    const int cpair = (lane & 3) * 2;
    #pragma unroll
    for (int i = 0; i < 2; ++i) {
        int gr0 = mBase + wm * 32 + i * 16 + q;
        #pragma unroll
        for (int j = 0; j < 8; ++j) {
            int gc = nBase + wn * 64 + j * 8 + cpair;
            if (gr0 < M)
                *(float2*)(C + (size_t)gr0 * ldc + gc) = make_float2(d[i][j][0], d[i][j][1]);
            if (gr0 + 8 < M)
                *(float2*)(C + (size_t)(gr0 + 8) * ldc + gc) = make_float2(d[i][j][2], d[i][j][3]);
        }
    }
}

// ---------------- split fp32 -> bf16 hi/lo ----------------
__global__ void split_k(const float* __restrict__ x, int n4,
                        __nv_bfloat16* __restrict__ hi, __nv_bfloat16* __restrict__ lo) {
    int i = blockIdx.x * blockDim.x + threadIdx.x;
    if (i >= n4) return;
    float4 v = ((const float4*)x)[i];
    __nv_bfloat16 h0, h1, h2, h3, l0, l1, l2, l3;
    split1(v.x, h0, l0); split1(v.y, h1, l1);
    split1(v.z, h2, l2); split1(v.w, h3, l3);
    ((uint2*)hi)[i] = make_uint2(pack_bf2(h0, h1), pack_bf2(h2, h3));
    ((uint2*)lo)[i] = make_uint2(pack_bf2(l0, l1), pack_bf2(l2, l3));
}

// ---------------- WcatT hi/lo: row n of [selfw | W_r] transposed ----------------
__global__ void build_wcatT(const float* __restrict__ bases,
                            const float* __restrict__ coeff,
                            const float* __restrict__ selfw,
                            __nv_bfloat16* __restrict__ Whi,
                            __nv_bfloat16* __restrict__ Wlo, int din) {
    int idx = blockIdx.x * blockDim.x + threadIdx.x;
    if (idx >= CAT * din) return;
    int n = idx / din;
    int k = idx - n * din;
    int blk = n >> 7;
    int j = n & 127;
    float v;
    if (blk == 0) {
        v = selfw[k * DHID + j];
    } else {
        int r = blk - 1;
        v = 0.f;
        #pragma unroll
        for (int b = 0; b < NBAS; ++b)
            v += coeff[r * NBAS + b] * bases[((size_t)b * din + k) * DHID + j];
    }
    __nv_bfloat16 h, l;
    split1(v, h, l);
    Whi[idx] = h;
    Wlo[idx] = l;
}

// ---------------- transpose head/tail blocks of w1, hi/lo ----------------
__global__ void transpose_w1(const float* __restrict__ w1,
                             __nv_bfloat16* __restrict__ hh, __nv_bfloat16* __restrict__ hl,
                             __nv_bfloat16* __restrict__ th, __nv_bfloat16* __restrict__ tl) {
    int idx = blockIdx.x * blockDim.x + threadIdx.x;
    if (idx >= DHID * DHID) return;
    int n = idx >> 7;
    int k = idx & 127;
    __nv_bfloat16 h, l;
    split1(w1[(size_t)k * DHID + n], h, l);
    hh[idx] = h; hl[idx] = l;
    split1(w1[(size_t)(384 + k) * DHID + n], h, l);
    th[idx] = h; tl[idx] = l;
}

// ---------------- init accumulator from self-loop block of Z ----------------
__global__ void init_self(const float* __restrict__ Z, float* __restrict__ acc) {
    int idx = blockIdx.x * blockDim.x + threadIdx.x;
    if (idx >= N_NODES * DHID) return;
    int n = idx >> 7;
    int j = idx & 127;
    acc[idx] = Z[(size_t)n * CAT + j];
}

// ---------------- edge scatter: acc[row] += Z[col, block(etype)] ----------------
__global__ void edge_scatter(const int* __restrict__ erow,
                             const int* __restrict__ ecol,
                             const int* __restrict__ etype,
                             const float* __restrict__ Z,
                             float* __restrict__ acc) {
    int e = blockIdx.x * 8 + (threadIdx.x >> 5);
    if (e >= NEDGE) return;
    int lane = threadIdx.x & 31;
    int r = erow[e], c = ecol[e], t = etype[e];
    float4 v = ((const float4*)(Z + (size_t)c * CAT + (size_t)(1 + t) * DHID))[lane];
    float* dst = acc + (size_t)r * DHID + lane * 4;
    atomicAdd(dst + 0, v.x);
    atomicAdd(dst + 1, v.y);
    atomicAdd(dst + 2, v.z);
    atomicAdd(dst + 3, v.w);
}

// ---------------- relu + layernorm -> bf16 hi/lo ----------------
__global__ void relu_ln(const float* __restrict__ acc,
                        const float* __restrict__ gamma,
                        const float* __restrict__ beta,
                        __nv_bfloat16* __restrict__ xhi,
                        __nv_bfloat16* __restrict__ xlo) {
    int n = blockIdx.x * 8 + (threadIdx.x >> 5);
    if (n >= N_NODES) return;
    int lane = threadIdx.x & 31;
    float4 v = ((const float4*)(acc + (size_t)n * DHID))[lane];
    v.x = fmaxf(v.x, 0.f); v.y = fmaxf(v.y, 0.f);
    v.z = fmaxf(v.z, 0.f); v.w = fmaxf(v.w, 0.f);
    float s = v.x + v.y + v.z + v.w;
    #pragma unroll
    for (int o = 16; o; o >>= 1) s += __shfl_xor_sync(0xFFFFFFFFu, s, o);
    float mu = s * (1.f / DHID);
    float dx = v.x - mu, dy = v.y - mu, dz = v.z - mu, dw = v.w - mu;
    float ss = dx * dx + dy * dy + dz * dz + dw * dw;
    #pragma unroll
    for (int o = 16; o; o >>= 1) ss += __shfl_xor_sync(0xFFFFFFFFu, ss, o);
    float inv = rsqrtf(ss * (1.f / DHID) + 1e-5f);
    float4 g = ((const float4*)gamma)[lane];
    float4 b = ((const float4*)beta)[lane];
    float ox = dx * inv * g.x + b.x;
    float oy = dy * inv * g.y + b.y;
    float oz = dz * inv * g.z + b.z;
    float ow = dw * inv * g.w + b.w;
    __nv_bfloat16 h0, h1, h2, h3, l0, l1, l2, l3;
    split1(ox, h0, l0); split1(oy, h1, l1);
    split1(oz, h2, l2); split1(ow, h3, l3);
    ((uint2*)(xhi + (size_t)n * DHID))[lane] = make_uint2(pack_bf2(h0, h1), pack_bf2(h2, h3));
    ((uint2*)(xlo + (size_t)n * DHID))[lane] = make_uint2(pack_bf2(l0, l1), pack_bf2(l2, l3));
}

// ---------------- relproj[r] = relation_emb[r] @ w1[128:384,:] + b1 ----------------
__global__ void relproj_k(const float* __restrict__ relemb,
                          const float* __restrict__ w1,
                          const float* __restrict__ b1,
                          float* __restrict__ rp) {
    int idx = blockIdx.x * blockDim.x + threadIdx.x;
    if (idx >= NREL * DHID) return;
    int r = idx >> 7;
    int j = idx & 127;
    float s = b1[j];
    for (int i = 0; i < DEMB; ++i)
        s = fmaf(relemb[r * DEMB + i], w1[(DHID + i) * DHID + j], s);
    rp[idx] = s;
}

// ---------------- score ----------------
__global__ void score_k(const int* __restrict__ head,
                        const int* __restrict__ rel,
                        const int* __restrict__ tail,
                        const float* __restrict__ HP,
                        const float* __restrict__ TP,
                        const float* __restrict__ rp,
                        const float* __restrict__ w2,
                        const float* __restrict__ b2,
                        float* __restrict__ out) {
    int q = blockIdx.x * 8 + (threadIdx.x >> 5);
    if (q >= NQUERY) return;
    int lane = threadIdx.x & 31;
    int h = head[q], r = rel[q], t = tail[q];
    float4 a = ((const float4*)(HP + (size_t)h * DHID))[lane];
    float4 bb = ((const float4*)(TP + (size_t)t * DHID))[lane];
    float4 c = ((const float4*)(rp + (size_t)r * DHID))[lane];
    float4 w = ((const float4*)w2)[lane];
    float s = fmaxf(a.x + bb.x + c.x, 0.f) * w.x
            + fmaxf(a.y + bb.y + c.y, 0.f) * w.y
            + fmaxf(a.z + bb.z + c.z, 0.f) * w.z
            + fmaxf(a.w + bb.w + c.w, 0.f) * w.w;
    #pragma unroll
    for (int o = 16; o; o >>= 1) s += __shfl_xor_sync(0xFFFFFFFFu, s, o);
    if (lane == 0) out[q] = s + b2[0];
}

// ---------------- launch ----------------
extern "C" void kernel_launch(void* const* d_in, const int* in_sizes, int n_in,
                              void* d_out, int out_size) {
    (void)in_sizes; (void)n_in; (void)out_size;
    const int*   edge_index   = (const int*)d_in[0];
    const int*   edge_type    = (const int*)d_in[1];
    const int*   head_ids     = (const int*)d_in[2];
    const int*   relation_ids = (const int*)d_in[3];
    const int*   tail_ids     = (const int*)d_in[4];
    const float* entity_emb   = (const float*)d_in[5];
    const float* relation_emb = (const float*)d_in[6];
    const float* bases0       = (const float*)d_in[7];
    const float* coeff0       = (const float*)d_in[8];
    const float* selfw0       = (const float*)d_in[9];
    const float* bases1       = (const float*)d_in[10];
    const float* coeff1       = (const float*)d_in[11];
    const float* selfw1       = (const float*)d_in[12];
    const float* ln0_g        = (const float*)d_in[13];
    const float* ln0_b        = (const float*)d_in[14];
    const float* ln1_g        = (const float*)d_in[15];
    const float* ln1_b        = (const float*)d_in[16];
    const float* w1           = (const float*)d_in[17];
    const float* b1           = (const float*)d_in[18];
    const float* w2           = (const float*)d_in[19];
    const float* b2           = (const float*)d_in[20];
    float* out = (float*)d_out;

    __nv_bfloat16 *Ehi, *Elo, *Whi, *Wlo, *xhi, *xlo, *w1hTh, *w1hTl, *w1tTh, *w1tTl;
    float *Z, *acc, *HP, *TP, *rp;
    cudaGetSymbolAddress((void**)&Ehi, g_Ehi);
    cudaGetSymbolAddress((void**)&Elo, g_Elo);
    cudaGetSymbolAddress((void**)&Whi, g_Whi);
    cudaGetSymbolAddress((void**)&Wlo, g_Wlo);
    cudaGetSymbolAddress((void**)&xhi, g_xhi);
    cudaGetSymbolAddress((void**)&xlo, g_xlo);
    cudaGetSymbolAddress((void**)&w1hTh, g_w1hTh);
    cudaGetSymbolAddress((void**)&w1hTl, g_w1hTl);
    cudaGetSymbolAddress((void**)&w1tTh, g_w1tTh);
    cudaGetSymbolAddress((void**)&w1tTl, g_w1tTl);
    cudaGetSymbolAddress((void**)&Z,   g_Z);
    cudaGetSymbolAddress((void**)&acc, g_acc);
    cudaGetSymbolAddress((void**)&HP,  g_HP);
    cudaGetSymbolAddress((void**)&TP,  g_TP);
    cudaGetSymbolAddress((void**)&rp,  g_rp);

    cudaFuncSetAttribute(gemm3xb, cudaFuncAttributeMaxDynamicSharedMemorySize, GEMM_SMEM);

    const int* erow = edge_index;
    const int* ecol = edge_index + NEDGE;

    dim3 gz(CAT / 128, (N_NODES + 127) / 128);   // 17 x 391
    dim3 gh(1, (N_NODES + 127) / 128);

    // ----- layer 0 -----
    split_k<<<(N_NODES * DEMB / 4 + 255) / 256, 256>>>(entity_emb, N_NODES * DEMB / 4, Ehi, Elo);
    build_wcatT<<<(CAT * DEMB + 255) / 256, 256>>>(bases0, coeff0, selfw0, Whi, Wlo, DEMB);
    gemm3xb<<<gz, 256, GEMM_SMEM>>>(N_NODES, DEMB, Ehi, Elo, Whi, Wlo, Z, CAT);
    init_self<<<(N_NODES * DHID + 255) / 256, 256>>>(Z, acc);
    edge_scatter<<<(NEDGE + 7) / 8, 256>>>(erow, ecol, edge_type, Z, acc);
    relu_ln<<<(N_NODES + 7) / 8, 256>>>(acc, ln0_g, ln0_b, xhi, xlo);

    // ----- layer 1 -----
    build_wcatT<<<(CAT * DHID + 255) / 256, 256>>>(bases1, coeff1, selfw1, Whi, Wlo, DHID);
    gemm3xb<<<gz, 256, GEMM_SMEM>>>(N_NODES, DHID, xhi, xlo, Whi, Wlo, Z, CAT);
    init_self<<<(N_NODES * DHID + 255) / 256, 256>>>(Z, acc);
    edge_scatter<<<(NEDGE + 7) / 8, 256>>>(erow, ecol, edge_type, Z, acc);
    relu_ln<<<(N_NODES + 7) / 8, 256>>>(acc, ln1_g, ln1_b, xhi, xlo);

    // ----- scoring -----
    relproj_k<<<(NREL * DHID + 255) / 256, 256>>>(relation_emb, w1, b1, rp);
    transpose_w1<<<(DHID * DHID + 255) / 256, 256>>>(w1, w1hTh, w1hTl, w1tTh, w1tTl);
    gemm3xb<<<gh, 256, GEMM_SMEM>>>(N_NODES, DHID, xhi, xlo, w1hTh, w1hTl, HP, DHID);
    gemm3xb<<<gh, 256, GEMM_SMEM>>>(N_NODES, DHID, xhi, xlo, w1tTh, w1tTl, TP, DHID);
    score_k<<<(NQUERY + 7) / 8, 256>>>(head_ids, relation_ids, tail_ids, HP, TP, rp, w2, b2, out);
}